// round 16
// baseline (speedup 1.0000x reference)
#include <cuda_runtime.h>
#include <cuda_bf16.h>

typedef unsigned int u32;

#define NTOK 16384
#define DDIM 2048
#define NEXP 64
#define TMB  64              // tokens per CTA
#define KC   64
#define NCHUNK (DDIM/KC)     // 32
#define NBLK (NTOK/TMB)      // 256
#define LSTR 66
#define TAU  1e-3f

// double-buffered smem layout (bytes): each tile 64x64 bf16 = 8KB
#define XHI(p) ((p) * 8192)
#define XLO(p) (16384 + (p) * 8192)
#define WHI(p) (32768 + (p) * 8192)
#define WLO(p) (49152 + (p) * 8192)
#define SMEM_BYTES 65536

// per-token fixup info: i1 | i2<<8 | i3<<16 | flag<<24
__device__ u32 g_info[NTOK];

static __device__ __forceinline__ u32 smem_u32(const void* p) {
    u32 a; asm("{ .reg .u64 t; cvta.to.shared.u64 t, %1; cvt.u32.u64 %0, t; }" : "=r"(a) : "l"(p));
    return a;
}
// pack (v0 -> low half, v1 -> high half)
static __device__ __forceinline__ u32 pack_bf16(float v0, float v1) {
    u32 r; asm("cvt.rn.bf16x2.f32 %0, %1, %2;" : "=r"(r) : "f"(v1), "f"(v0)); return r;
}

#define LDM_X4(r0,r1,r2,r3, addr) \
    asm volatile("ldmatrix.sync.aligned.m8n8.x4.shared.b16 {%0,%1,%2,%3}, [%4];" \
        : "=r"(r0),"=r"(r1),"=r"(r2),"=r"(r3) : "r"(addr))

#define MMA16816(d, a, b0, b1) \
    asm volatile("mma.sync.aligned.m16n8k16.row.col.f32.bf16.bf16.f32 " \
        "{%0,%1,%2,%3}, {%4,%5,%6,%7}, {%8,%9}, {%0,%1,%2,%3};" \
        : "+f"((d)[0]),"+f"((d)[1]),"+f"((d)[2]),"+f"((d)[3]) \
        : "r"((a)[0]),"r"((a)[1]),"r"((a)[2]),"r"((a)[3]),"r"(b0),"r"(b1))

__global__ __launch_bounds__(256, 2) void moe_main(
    const float* __restrict__ x,
    const float* __restrict__ W,
    const float* __restrict__ sc,
    const float* __restrict__ noise,
    const int*   __restrict__ sidx_p,
    float*       __restrict__ out,
    int do_probs, int do_idx)
{
    extern __shared__ __align__(16) char dsm[];
    const u32 sb = smem_u32(dsm);

    const int t   = threadIdx.x;
    const int wid = t >> 5;
    const int lid = t & 31;

    // warp tile: m0 in {0,16,32,48} (m16), n0 in {0,32} (n32)
    const int m0 = (wid >> 1) * 16;
    const int n0 = (wid & 1) * 32;
    const int tokA = lid & 15;
    const int kqA  = lid >> 4;
    const int eB   = (lid & 7) + ((lid >> 4) << 3);
    const int kqB  = (lid >> 3) & 1;

    // loaders: x (64 tok) and W (64 exp) tiles are 64x64 f32 per chunk;
    // thread covers row = t>>2, k-quarter (t&3)*16
    const int lrow = t >> 2;
    const int lq   = t & 3;
    const float* xg = x + (long)blockIdx.x * TMB * DDIM + (long)lrow * DDIM + lq * 16;
    const float* wg = W + (long)lrow * DDIM + lq * 16;
    const u32 tsb = (u32)lrow * 128u + (u32)lq * 32u;
    const u32 swz = ((u32)lrow & 7u) << 4;

    float acc[4][4];
#pragma unroll
    for (int j = 0; j < 4; ++j)
#pragma unroll
        for (int r = 0; r < 4; ++r) acc[j][r] = 0.0f;

    float4 xr[4], wr[4];

    auto conv8 = [&](float4 a, float4 b, uint4& hi, uint4& lo) {
        u32 h01 = pack_bf16(a.x, a.y);
        u32 h23 = pack_bf16(a.z, a.w);
        u32 h45 = pack_bf16(b.x, b.y);
        u32 h67 = pack_bf16(b.z, b.w);
        float f0 = __uint_as_float(h01 << 16), f1 = __uint_as_float(h01 & 0xffff0000u);
        float f2 = __uint_as_float(h23 << 16), f3 = __uint_as_float(h23 & 0xffff0000u);
        float f4 = __uint_as_float(h45 << 16), f5 = __uint_as_float(h45 & 0xffff0000u);
        float f6 = __uint_as_float(h67 << 16), f7 = __uint_as_float(h67 & 0xffff0000u);
        hi = make_uint4(h01, h23, h45, h67);
        lo = make_uint4(pack_bf16(a.x - f0, a.y - f1),
                        pack_bf16(a.z - f2, a.w - f3),
                        pack_bf16(b.x - f4, b.y - f5),
                        pack_bf16(b.z - f6, b.w - f7));
    };

    auto store_tiles = [&](int p) {
#pragma unroll
        for (int qq = 0; qq < 2; ++qq) {
            uint4 hi, lo;
            u32 sw = (tsb + (u32)qq * 16u) ^ swz;
            conv8(xr[2 * qq], xr[2 * qq + 1], hi, lo);
            *(uint4*)(dsm + XHI(p) + sw) = hi;
            *(uint4*)(dsm + XLO(p) + sw) = lo;
            conv8(wr[2 * qq], wr[2 * qq + 1], hi, lo);
            *(uint4*)(dsm + WHI(p) + sw) = hi;
            *(uint4*)(dsm + WLO(p) + sw) = lo;
        }
    };

    auto load_chunk = [&](int c) {
        const float* xb = xg + c * KC;
        const float* wb = wg + c * KC;
#pragma unroll
        for (int q = 0; q < 4; ++q) xr[q] = *(const float4*)(xb + q * 4);
#pragma unroll
        for (int q = 0; q < 4; ++q) wr[q] = *(const float4*)(wb + q * 4);
    };

    // prologue
    load_chunk(0);
    store_tiles(0);
    load_chunk(1);
    __syncthreads();

#pragma unroll 1
    for (int it = 0; it < NCHUNK; ++it) {
        const int p = it & 1;

        if (it + 1 < NCHUNK) store_tiles(p ^ 1);   // stage chunk it+1
        if (it + 2 < NCHUNK) load_chunk(it + 2);   // LDG chunk it+2 under MMAs

#pragma unroll
        for (int kk = 0; kk < 4; ++kk) {
            u32 ah[4], al[4], bh[8], bl[8];
            {
                int tok = m0 + tokA;
                u32 sw = (u32)(((kk * 2 + kqA) ^ (tokA & 7)) << 4);
                u32 aaddr = sb + XHI(p) + (u32)tok * 128u + sw;
                LDM_X4(ah[0], ah[1], ah[2], ah[3], aaddr);
                LDM_X4(al[0], al[1], al[2], al[3], aaddr + 16384u);
            }
#pragma unroll
            for (int ng = 0; ng < 2; ++ng) {
                int ef = n0 + ng * 16 + eB;
                u32 sw = (u32)(((kk * 2 + kqB) ^ (eB & 7)) << 4);
                u32 baddr = sb + WHI(p) + (u32)ef * 128u + sw;
                LDM_X4(bh[ng*4+0], bh[ng*4+1], bh[ng*4+2], bh[ng*4+3], baddr);
                LDM_X4(bl[ng*4+0], bl[ng*4+1], bl[ng*4+2], bl[ng*4+3], baddr + 16384u);
            }
            // three sweeps: dependent MMAs on any acc[j] are 4 issues apart;
            // per-acc term order stays hh,hl,lh -> bit-identical to grouped order
#pragma unroll
            for (int j = 0; j < 4; ++j) {            // hi*hi
                int bi = (j >> 1) * 4 + (j & 1) * 2;
                MMA16816(acc[j], ah, bh[bi], bh[bi + 1]);
            }
#pragma unroll
            for (int j = 0; j < 4; ++j) {            // hi*lo
                int bi = (j >> 1) * 4 + (j & 1) * 2;
                MMA16816(acc[j], ah, bl[bi], bl[bi + 1]);
            }
#pragma unroll
            for (int j = 0; j < 4; ++j) {            // lo*hi
                int bi = (j >> 1) * 4 + (j & 1) * 2;
                MMA16816(acc[j], al, bh[bi], bh[bi + 1]);
            }
        }

        __syncthreads();
    }

    // ---- spill accumulators into (reused) dynamic smem: [tok][e] ----
    {
        float* lg = (float*)dsm;
        const int r  = lid >> 2;
        const int c2 = (lid & 3) * 2;
#pragma unroll
        for (int j = 0; j < 4; ++j) {
            int tok = m0 + r;
            int e   = n0 + j * 8 + c2;
            lg[tok * LSTR + e]           = acc[j][0];
            lg[tok * LSTR + e + 1]       = acc[j][1];
            lg[(tok + 8) * LSTR + e]     = acc[j][2];
            lg[(tok + 8) * LSTR + e + 1] = acc[j][3];
        }
    }
    __syncthreads();

    // ---- epilogue: one token per thread (t < 64); NO guard here ----
    if (t < TMB) {
        const long tokg = (long)blockIdx.x * TMB + t;
        const float f = 1.0f + 0.1f * sc[sidx_p[0]];
        const float* lrow = (const float*)dsm + t * LSTR;
        const float4* nz = (const float4*)(noise + tokg * NEXP);

        float lr[NEXP];
        float m = -1e30f;
#pragma unroll
        for (int q = 0; q < 16; ++q) {
            float4 nv = nz[q];
            float v0 = fmaf(f, lrow[q * 4 + 0], 0.1f * nv.x);
            float v1 = fmaf(f, lrow[q * 4 + 1], 0.1f * nv.y);
            float v2 = fmaf(f, lrow[q * 4 + 2], 0.1f * nv.z);
            float v3 = fmaf(f, lrow[q * 4 + 3], 0.1f * nv.w);
            lr[q * 4 + 0] = v0; lr[q * 4 + 1] = v1;
            lr[q * 4 + 2] = v2; lr[q * 4 + 3] = v3;
            m = fmaxf(m, fmaxf(fmaxf(v0, v1), fmaxf(v2, v3)));
        }

        // top-3 on raw logits (strict >: lowest index wins ties)
        float b1 = -1e30f, b2 = -1e30f, b3 = -1e30f;
        int   i1 = 0,      i2 = 0,      i3 = 0;
#pragma unroll
        for (int e = 0; e < NEXP; ++e) {
            float v = lr[e];
            if (v > b1)      { b3 = b2; i3 = i2; b2 = b1; i2 = i1; b1 = v; i1 = e; }
            else if (v > b2) { b3 = b2; i3 = i2; b2 = v;  i2 = e; }
            else if (v > b3) { b3 = v;  i3 = e; }
        }

        // flag near-ties for the separate fixup kernel
        u32 flag = ((b1 - b2 < TAU) || (b2 - b3 < TAU)) ? 1u : 0u;
        g_info[tokg] = (u32)i1 | ((u32)i2 << 8) | ((u32)i3 << 16) | (flag << 24);

        float sum = 0.0f;
#pragma unroll
        for (int e = 0; e < NEXP; ++e) {
            float pb = __expf(lr[e] - m);
            lr[e] = pb;
            sum += pb;
        }
        const float inv = 1.0f / sum;
        const float p1  = __expf(b1 - m);
        const float p2  = __expf(b2 - m);
        const float wn  = 1.0f / (p1 + p2);
        const float w1v = p1 * wn, w2v = p2 * wn;

        float4* disp = (float4*)out + tokg * 16;
#pragma unroll
        for (int q = 0; q < 16; ++q) {
            float4 z = make_float4(0.f, 0.f, 0.f, 0.f);
            if ((i1 >> 2) == q) (&z.x)[i1 & 3] = w1v;
            if ((i2 >> 2) == q) (&z.x)[i2 & 3] = w2v;
            disp[q] = z;
        }
        if (do_probs) {
            float4* pr = (float4*)(out + (long)NTOK * NEXP) + tokg * 16;
#pragma unroll
            for (int q = 0; q < 16; ++q) {
                float4 z;
                z.x = lr[q * 4 + 0] * inv;
                z.y = lr[q * 4 + 1] * inv;
                z.z = lr[q * 4 + 2] * inv;
                z.w = lr[q * 4 + 3] * inv;
                pr[q] = z;
            }
        }
        if (do_idx) {
            float* ix = out + 2L * NTOK * NEXP + tokg * 2;
            ix[0] = (float)i1;
            ix[1] = (float)i2;
        }
    }
}

// ---- fixup kernel: exact f32 recompute for flagged (near-tie) tokens ----
__global__ __launch_bounds__(256) void moe_fixup(
    const float* __restrict__ x,
    const float* __restrict__ W,
    const float* __restrict__ sc,
    const float* __restrict__ noise,
    const int*   __restrict__ sidx_p,
    float*       __restrict__ out,
    int do_idx)
{
    const int tok = blockIdx.x * 256 + threadIdx.x;
    const u32 info = g_info[tok];
    if (!(info >> 24)) return;

    const int ia = info & 255, ib = (info >> 8) & 255, ic = (info >> 16) & 255;
    const float f = 1.0f + 0.1f * sc[sidx_p[0]];
    const float* nrow = noise + (long)tok * NEXP;

    const float4* xa = (const float4*)(x + (long)tok * DDIM);
    const float4* wa = (const float4*)(W + (long)ia * DDIM);
    const float4* wb = (const float4*)(W + (long)ib * DDIM);
    const float4* wc = (const float4*)(W + (long)ic * DDIM);
    float4 sA = make_float4(0.f,0.f,0.f,0.f);
    float4 sB = make_float4(0.f,0.f,0.f,0.f);
    float4 sC = make_float4(0.f,0.f,0.f,0.f);
    for (int i = 0; i < DDIM / 4; ++i) {
        float4 xv = xa[i];
        float4 w1 = wa[i], w2 = wb[i], w3 = wc[i];
        sA.x = fmaf(xv.x, w1.x, sA.x); sA.y = fmaf(xv.y, w1.y, sA.y);
        sA.z = fmaf(xv.z, w1.z, sA.z); sA.w = fmaf(xv.w, w1.w, sA.w);
        sB.x = fmaf(xv.x, w2.x, sB.x); sB.y = fmaf(xv.y, w2.y, sB.y);
        sB.z = fmaf(xv.z, w2.z, sB.z); sB.w = fmaf(xv.w, w2.w, sB.w);
        sC.x = fmaf(xv.x, w3.x, sC.x); sC.y = fmaf(xv.y, w3.y, sC.y);
        sC.z = fmaf(xv.z, w3.z, sC.z); sC.w = fmaf(xv.w, w3.w, sC.w);
    }
    float v[3];
    int   id[3] = {ia, ib, ic};
    v[0] = fmaf(f, (sA.x + sA.y) + (sA.z + sA.w), 0.1f * nrow[ia]);
    v[1] = fmaf(f, (sB.x + sB.y) + (sB.z + sB.w), 0.1f * nrow[ib]);
    v[2] = fmaf(f, (sC.x + sC.y) + (sC.z + sC.w), 0.1f * nrow[ic]);
    // sort 3 by (value desc, index asc): network (0,1),(1,2),(0,1)
#pragma unroll
    for (int s3 = 0; s3 < 3; ++s3) {
        int a = (s3 == 1) ? 1 : 0, b = a + 1;
        bool sw = (v[b] > v[a]) || (v[b] == v[a] && id[b] < id[a]);
        if (sw) {
            float tv = v[a]; v[a] = v[b]; v[b] = tv;
            int ti = id[a]; id[a] = id[b]; id[b] = ti;
        }
    }
    const int i1 = id[0], i2 = id[1];
    // softmax-pair weights from exact logits: w1 = p1/(p1+p2)
    const float e2  = expf(v[1] - v[0]);
    const float w1v = 1.0f / (1.0f + e2);
    const float w2v = e2 * w1v;

    float4* disp = (float4*)out + (long)tok * 16;
#pragma unroll
    for (int q = 0; q < 16; ++q) {
        float4 z = make_float4(0.f, 0.f, 0.f, 0.f);
        if ((i1 >> 2) == q) (&z.x)[i1 & 3] = w1v;
        if ((i2 >> 2) == q) (&z.x)[i2 & 3] = w2v;
        disp[q] = z;
    }
    if (do_idx) {
        float* ix = out + 2L * NTOK * NEXP + (long)tok * 2;
        ix[0] = (float)i1;
        ix[1] = (float)i2;
    }
}

extern "C" void kernel_launch(void* const* d_in, const int* in_sizes, int n_in,
                              void* d_out, int out_size) {
    const float* x     = (const float*)d_in[0];
    const float* W     = (const float*)d_in[1];
    const float* sc    = (const float*)d_in[2];
    const float* noise = (const float*)d_in[3];
    const int*   sidx  = (const int*)d_in[4];
    float* out = (float*)d_out;

    const int do_probs = (out_size >= 2 * NTOK * NEXP) ? 1 : 0;
    const int do_idx   = (out_size >= 2 * NTOK * NEXP + 2 * NTOK) ? 1 : 0;

    cudaFuncSetAttribute(moe_main, cudaFuncAttributeMaxDynamicSharedMemorySize, SMEM_BYTES);
    moe_main<<<NBLK, 256, SMEM_BYTES>>>(x, W, sc, noise, sidx, out, do_probs, do_idx);
    moe_fixup<<<NTOK / 256, 256>>>(x, W, sc, noise, sidx, out, do_idx);
}

// round 17
// speedup vs baseline: 1.7706x; 1.7706x over previous
#include <cuda_runtime.h>
#include <cuda_bf16.h>

typedef unsigned int u32;

#define NTOK 16384
#define DDIM 2048
#define NEXP 64
#define TMB  64              // tokens per CTA
#define KC   64
#define NCHUNK (DDIM/KC)     // 32
#define NBLK (NTOK/TMB)      // 256
#define LSTR 66
#define TAU  2e-4f

// double-buffered smem layout (bytes): each tile 64x64 bf16 = 8KB
#define XHI(p) ((p) * 8192)
#define XLO(p) (16384 + (p) * 8192)
#define WHI(p) (32768 + (p) * 8192)
#define WLO(p) (49152 + (p) * 8192)
#define SMEM_BYTES 65536

// per-token fixup info: i1 | i2<<8 | i3<<16 | flag<<24
__device__ u32 g_info[NTOK];

static __device__ __forceinline__ u32 smem_u32(const void* p) {
    u32 a; asm("{ .reg .u64 t; cvta.to.shared.u64 t, %1; cvt.u32.u64 %0, t; }" : "=r"(a) : "l"(p));
    return a;
}
// pack (v0 -> low half, v1 -> high half)
static __device__ __forceinline__ u32 pack_bf16(float v0, float v1) {
    u32 r; asm("cvt.rn.bf16x2.f32 %0, %1, %2;" : "=r"(r) : "f"(v1), "f"(v0)); return r;
}

#define LDM_X4(r0,r1,r2,r3, addr) \
    asm volatile("ldmatrix.sync.aligned.m8n8.x4.shared.b16 {%0,%1,%2,%3}, [%4];" \
        : "=r"(r0),"=r"(r1),"=r"(r2),"=r"(r3) : "r"(addr))

#define MMA16816(d, a, b0, b1) \
    asm volatile("mma.sync.aligned.m16n8k16.row.col.f32.bf16.bf16.f32 " \
        "{%0,%1,%2,%3}, {%4,%5,%6,%7}, {%8,%9}, {%0,%1,%2,%3};" \
        : "+f"((d)[0]),"+f"((d)[1]),"+f"((d)[2]),"+f"((d)[3]) \
        : "r"((a)[0]),"r"((a)[1]),"r"((a)[2]),"r"((a)[3]),"r"(b0),"r"(b1))

__global__ __launch_bounds__(256, 2) void moe_main(
    const float* __restrict__ x,
    const float* __restrict__ W,
    const float* __restrict__ sc,
    const float* __restrict__ noise,
    const int*   __restrict__ sidx_p,
    float*       __restrict__ out,
    int do_probs, int do_idx)
{
    extern __shared__ __align__(16) char dsm[];
    const u32 sb = smem_u32(dsm);

    const int t   = threadIdx.x;
    const int wid = t >> 5;
    const int lid = t & 31;

    // warp tile: m0 in {0,16,32,48} (m16), n0 in {0,32} (n32)
    const int m0 = (wid >> 1) * 16;
    const int n0 = (wid & 1) * 32;
    const int tokA = lid & 15;
    const int kqA  = lid >> 4;
    const int eB   = (lid & 7) + ((lid >> 4) << 3);
    const int kqB  = (lid >> 3) & 1;

    // loaders: x (64 tok) and W (64 exp) tiles are 64x64 f32 per chunk;
    // thread covers row = t>>2, k-quarter (t&3)*16
    const int lrow = t >> 2;
    const int lq   = t & 3;
    const float* xg = x + (long)blockIdx.x * TMB * DDIM + (long)lrow * DDIM + lq * 16;
    const float* wg = W + (long)lrow * DDIM + lq * 16;
    const u32 tsb = (u32)lrow * 128u + (u32)lq * 32u;
    const u32 swz = ((u32)lrow & 7u) << 4;

    float acc[4][4];
#pragma unroll
    for (int j = 0; j < 4; ++j)
#pragma unroll
        for (int r = 0; r < 4; ++r) acc[j][r] = 0.0f;

    float4 xr[4], wr[4];

    auto conv8 = [&](float4 a, float4 b, uint4& hi, uint4& lo) {
        u32 h01 = pack_bf16(a.x, a.y);
        u32 h23 = pack_bf16(a.z, a.w);
        u32 h45 = pack_bf16(b.x, b.y);
        u32 h67 = pack_bf16(b.z, b.w);
        float f0 = __uint_as_float(h01 << 16), f1 = __uint_as_float(h01 & 0xffff0000u);
        float f2 = __uint_as_float(h23 << 16), f3 = __uint_as_float(h23 & 0xffff0000u);
        float f4 = __uint_as_float(h45 << 16), f5 = __uint_as_float(h45 & 0xffff0000u);
        float f6 = __uint_as_float(h67 << 16), f7 = __uint_as_float(h67 & 0xffff0000u);
        hi = make_uint4(h01, h23, h45, h67);
        lo = make_uint4(pack_bf16(a.x - f0, a.y - f1),
                        pack_bf16(a.z - f2, a.w - f3),
                        pack_bf16(b.x - f4, b.y - f5),
                        pack_bf16(b.z - f6, b.w - f7));
    };

    auto store_tiles = [&](int p) {
#pragma unroll
        for (int qq = 0; qq < 2; ++qq) {
            uint4 hi, lo;
            u32 sw = (tsb + (u32)qq * 16u) ^ swz;
            conv8(xr[2 * qq], xr[2 * qq + 1], hi, lo);
            *(uint4*)(dsm + XHI(p) + sw) = hi;
            *(uint4*)(dsm + XLO(p) + sw) = lo;
            conv8(wr[2 * qq], wr[2 * qq + 1], hi, lo);
            *(uint4*)(dsm + WHI(p) + sw) = hi;
            *(uint4*)(dsm + WLO(p) + sw) = lo;
        }
    };

    auto load_chunk = [&](int c) {
        const float* xb = xg + c * KC;
        const float* wb = wg + c * KC;
#pragma unroll
        for (int q = 0; q < 4; ++q) xr[q] = *(const float4*)(xb + q * 4);
#pragma unroll
        for (int q = 0; q < 4; ++q) wr[q] = *(const float4*)(wb + q * 4);
    };

    // prologue
    load_chunk(0);
    store_tiles(0);
    load_chunk(1);
    __syncthreads();

#pragma unroll 1
    for (int it = 0; it < NCHUNK; ++it) {
        const int p = it & 1;

        if (it + 1 < NCHUNK) store_tiles(p ^ 1);   // stage chunk it+1
        if (it + 2 < NCHUNK) load_chunk(it + 2);   // LDG chunk it+2 under MMAs

#pragma unroll
        for (int kk = 0; kk < 4; ++kk) {
            u32 ah[4], al[4], bh[8], bl[8];
            {
                int tok = m0 + tokA;
                u32 sw = (u32)(((kk * 2 + kqA) ^ (tokA & 7)) << 4);
                u32 aaddr = sb + XHI(p) + (u32)tok * 128u + sw;
                LDM_X4(ah[0], ah[1], ah[2], ah[3], aaddr);
                LDM_X4(al[0], al[1], al[2], al[3], aaddr + 16384u);
            }
#pragma unroll
            for (int ng = 0; ng < 2; ++ng) {
                int ef = n0 + ng * 16 + eB;
                u32 sw = (u32)(((kk * 2 + kqB) ^ (eB & 7)) << 4);
                u32 baddr = sb + WHI(p) + (u32)ef * 128u + sw;
                LDM_X4(bh[ng*4+0], bh[ng*4+1], bh[ng*4+2], bh[ng*4+3], baddr);
                LDM_X4(bl[ng*4+0], bl[ng*4+1], bl[ng*4+2], bl[ng*4+3], baddr + 16384u);
            }
            // three sweeps: dependent MMAs on any acc[j] are 4 issues apart;
            // per-acc term order stays hh,hl,lh -> bit-identical to grouped order
#pragma unroll
            for (int j = 0; j < 4; ++j) {            // hi*hi
                int bi = (j >> 1) * 4 + (j & 1) * 2;
                MMA16816(acc[j], ah, bh[bi], bh[bi + 1]);
            }
#pragma unroll
            for (int j = 0; j < 4; ++j) {            // hi*lo
                int bi = (j >> 1) * 4 + (j & 1) * 2;
                MMA16816(acc[j], ah, bl[bi], bl[bi + 1]);
            }
#pragma unroll
            for (int j = 0; j < 4; ++j) {            // lo*hi
                int bi = (j >> 1) * 4 + (j & 1) * 2;
                MMA16816(acc[j], al, bh[bi], bh[bi + 1]);
            }
        }

        __syncthreads();
    }

    // ---- spill accumulators into (reused) dynamic smem: [tok][e] ----
    {
        float* lg = (float*)dsm;
        const int r  = lid >> 2;
        const int c2 = (lid & 3) * 2;
#pragma unroll
        for (int j = 0; j < 4; ++j) {
            int tok = m0 + r;
            int e   = n0 + j * 8 + c2;
            lg[tok * LSTR + e]           = acc[j][0];
            lg[tok * LSTR + e + 1]       = acc[j][1];
            lg[(tok + 8) * LSTR + e]     = acc[j][2];
            lg[(tok + 8) * LSTR + e + 1] = acc[j][3];
        }
    }
    __syncthreads();

    // ---- epilogue: one token per thread (t < 64); NO guard here ----
    if (t < TMB) {
        const long tokg = (long)blockIdx.x * TMB + t;
        const float f = 1.0f + 0.1f * sc[sidx_p[0]];
        const float* lrowp = (const float*)dsm + t * LSTR;
        const float4* nz = (const float4*)(noise + tokg * NEXP);

        float lr[NEXP];
        float m = -1e30f;
#pragma unroll
        for (int q = 0; q < 16; ++q) {
            float4 nv = nz[q];
            float v0 = fmaf(f, lrowp[q * 4 + 0], 0.1f * nv.x);
            float v1 = fmaf(f, lrowp[q * 4 + 1], 0.1f * nv.y);
            float v2 = fmaf(f, lrowp[q * 4 + 2], 0.1f * nv.z);
            float v3 = fmaf(f, lrowp[q * 4 + 3], 0.1f * nv.w);
            lr[q * 4 + 0] = v0; lr[q * 4 + 1] = v1;
            lr[q * 4 + 2] = v2; lr[q * 4 + 3] = v3;
            m = fmaxf(m, fmaxf(fmaxf(v0, v1), fmaxf(v2, v3)));
        }

        // top-3 on raw logits (strict >: lowest index wins ties)
        float b1 = -1e30f, b2 = -1e30f, b3 = -1e30f;
        int   i1 = 0,      i2 = 0,      i3 = 0;
#pragma unroll
        for (int e = 0; e < NEXP; ++e) {
            float v = lr[e];
            if (v > b1)      { b3 = b2; i3 = i2; b2 = b1; i2 = i1; b1 = v; i1 = e; }
            else if (v > b2) { b3 = b2; i3 = i2; b2 = v;  i2 = e; }
            else if (v > b3) { b3 = v;  i3 = e; }
        }

        // flag near-ties for the separate fixup kernel
        u32 flag = ((b1 - b2 < TAU) || (b2 - b3 < TAU)) ? 1u : 0u;
        g_info[tokg] = (u32)i1 | ((u32)i2 << 8) | ((u32)i3 << 16) | (flag << 24);

        float sum = 0.0f;
#pragma unroll
        for (int e = 0; e < NEXP; ++e) {
            float pb = __expf(lr[e] - m);
            lr[e] = pb;
            sum += pb;
        }
        const float inv = 1.0f / sum;
        const float p1  = __expf(b1 - m);
        const float p2  = __expf(b2 - m);
        const float wn  = 1.0f / (p1 + p2);
        const float w1v = p1 * wn, w2v = p2 * wn;

        float4* disp = (float4*)out + tokg * 16;
#pragma unroll
        for (int q = 0; q < 16; ++q) {
            float4 z = make_float4(0.f, 0.f, 0.f, 0.f);
            if ((i1 >> 2) == q) (&z.x)[i1 & 3] = w1v;
            if ((i2 >> 2) == q) (&z.x)[i2 & 3] = w2v;
            disp[q] = z;
        }
        if (do_probs) {
            float4* pr = (float4*)(out + (long)NTOK * NEXP) + tokg * 16;
#pragma unroll
            for (int q = 0; q < 16; ++q) {
                float4 z;
                z.x = lr[q * 4 + 0] * inv;
                z.y = lr[q * 4 + 1] * inv;
                z.z = lr[q * 4 + 2] * inv;
                z.w = lr[q * 4 + 3] * inv;
                pr[q] = z;
            }
        }
        if (do_idx) {
            float* ix = out + 2L * NTOK * NEXP + tokg * 2;
            ix[0] = (float)i1;
            ix[1] = (float)i2;
        }
    }
}

// ---- fixup kernel: WARP-cooperative exact f32 recompute for flagged tokens ----
__global__ __launch_bounds__(256) void moe_fixup(
    const float* __restrict__ x,
    const float* __restrict__ W,
    const float* __restrict__ sc,
    const float* __restrict__ noise,
    const int*   __restrict__ sidx_p,
    float*       __restrict__ out,
    int do_idx)
{
    const int wid = threadIdx.x >> 5;
    const int lid = threadIdx.x & 31;
    const int tok = blockIdx.x * 8 + wid;    // one warp per token
    const u32 info = g_info[tok];
    if (!(info >> 24)) return;               // warp-uniform early exit

    const int ia = info & 255, ib = (info >> 8) & 255, ic = (info >> 16) & 255;
    const float f = 1.0f + 0.1f * sc[sidx_p[0]];
    const float* nrow = noise + (long)tok * NEXP;

    // warp-parallel triple dot: lane covers float4 index lid + 32*it
    const float4* xa = (const float4*)(x + (long)tok * DDIM);
    const float4* wa = (const float4*)(W + (long)ia * DDIM);
    const float4* wb = (const float4*)(W + (long)ib * DDIM);
    const float4* wc = (const float4*)(W + (long)ic * DDIM);
    float sA = 0.f, sB = 0.f, sC = 0.f;
#pragma unroll
    for (int it = 0; it < 16; ++it) {
        int i = it * 32 + lid;
        float4 xv = xa[i];
        float4 w1 = wa[i], w2 = wb[i], w3 = wc[i];
        sA = fmaf(xv.x, w1.x, fmaf(xv.y, w1.y, fmaf(xv.z, w1.z, fmaf(xv.w, w1.w, sA))));
        sB = fmaf(xv.x, w2.x, fmaf(xv.y, w2.y, fmaf(xv.z, w2.z, fmaf(xv.w, w2.w, sB))));
        sC = fmaf(xv.x, w3.x, fmaf(xv.y, w3.y, fmaf(xv.z, w3.z, fmaf(xv.w, w3.w, sC))));
    }
#pragma unroll
    for (int o = 16; o; o >>= 1) {
        sA += __shfl_xor_sync(0xffffffffu, sA, o);
        sB += __shfl_xor_sync(0xffffffffu, sB, o);
        sC += __shfl_xor_sync(0xffffffffu, sC, o);
    }

    // rank on lane 0, broadcast result
    float v[3];
    int   id[3] = {ia, ib, ic};
    v[0] = fmaf(f, sA, 0.1f * nrow[ia]);
    v[1] = fmaf(f, sB, 0.1f * nrow[ib]);
    v[2] = fmaf(f, sC, 0.1f * nrow[ic]);
    // sort 3 by (value desc, index asc): network (0,1),(1,2),(0,1)
#pragma unroll
    for (int s3 = 0; s3 < 3; ++s3) {
        int a = (s3 == 1) ? 1 : 0, b = a + 1;
        bool sw = (v[b] > v[a]) || (v[b] == v[a] && id[b] < id[a]);
        if (sw) {
            float tv = v[a]; v[a] = v[b]; v[b] = tv;
            int ti = id[a]; id[a] = id[b]; id[b] = ti;
        }
    }
    const int i1 = id[0], i2 = id[1];
    const float e2  = expf(v[1] - v[0]);
    const float w1v = 1.0f / (1.0f + e2);
    const float w2v = e2 * w1v;

    // lanes 0..15 write one float4 each of the dispatch row
    if (lid < 16) {
        float4 z = make_float4(0.f, 0.f, 0.f, 0.f);
        if ((i1 >> 2) == lid) (&z.x)[i1 & 3] = w1v;
        if ((i2 >> 2) == lid) (&z.x)[i2 & 3] = w2v;
        ((float4*)out)[(long)tok * 16 + lid] = z;
    }
    if (do_idx && lid == 0) {
        float* ix = out + 2L * NTOK * NEXP + (long)tok * 2;
        ix[0] = (float)i1;
        ix[1] = (float)i2;
    }
}

extern "C" void kernel_launch(void* const* d_in, const int* in_sizes, int n_in,
                              void* d_out, int out_size) {
    const float* x     = (const float*)d_in[0];
    const float* W     = (const float*)d_in[1];
    const float* sc    = (const float*)d_in[2];
    const float* noise = (const float*)d_in[3];
    const int*   sidx  = (const int*)d_in[4];
    float* out = (float*)d_out;

    const int do_probs = (out_size >= 2 * NTOK * NEXP) ? 1 : 0;
    const int do_idx   = (out_size >= 2 * NTOK * NEXP + 2 * NTOK) ? 1 : 0;

    cudaFuncSetAttribute(moe_main, cudaFuncAttributeMaxDynamicSharedMemorySize, SMEM_BYTES);
    moe_main<<<NBLK, 256, SMEM_BYTES>>>(x, W, sc, noise, sidx, out, do_probs, do_idx);
    moe_fixup<<<NTOK / 8, 256>>>(x, W, sc, noise, sidx, out, do_idx);
}